// round 1
// baseline (speedup 1.0000x reference)
#include <cuda_runtime.h>
#include <cfloat>

#define N_Q   2048
#define M_B   100000
#define DIM   128
#define KNN   5
#define SPLITS 9
#define QT    64
#define BT    64
#define TPB   256

#define ROWS_PER_SPLIT ((M_B + SPLITS - 1) / SPLITS)      /* 11112 */
#define TILES_PER_SPLIT ((ROWS_PER_SPLIT + BT - 1) / BT)  /* 174   */

typedef unsigned long long u64;

// scratch (no allocation allowed)
__device__ float g_y2[M_B];
__device__ float g_scratch[N_Q * SPLITS * KNN];

// ---------------------------------------------------------------------------
// Kernel 1: y2[m] = ||bank[m]||^2   (one warp per row, float4 + shfl reduce)
// ---------------------------------------------------------------------------
__global__ void y2_kernel(const float* __restrict__ bank) {
    int gw = (blockIdx.x * blockDim.x + threadIdx.x) >> 5;
    int lane = threadIdx.x & 31;
    if (gw >= M_B) return;
    float4 v = *reinterpret_cast<const float4*>(bank + (size_t)gw * DIM + lane * 4);
    float s = v.x * v.x + v.y * v.y + v.z * v.z + v.w * v.w;
    #pragma unroll
    for (int o = 16; o; o >>= 1) s += __shfl_xor_sync(0xFFFFFFFFu, s, o);
    if (lane == 0) g_y2[gw] = s;
}

// ---------------------------------------------------------------------------
// sorted top-5 insert (t ascending, t[4] = current max). Only called when
// d < t[4], so a single bubble pass restores order.
// ---------------------------------------------------------------------------
__device__ __forceinline__ void insert5(float* t, float d) {
    t[4] = d;
    #pragma unroll
    for (int s = 4; s > 0; --s) {
        float lo = fminf(t[s], t[s - 1]);
        float hi = fmaxf(t[s], t[s - 1]);
        t[s - 1] = lo;
        t[s]     = hi;
    }
}

__device__ __forceinline__ void fma2(u64& acc, u64 a, u64 b) {
    asm("fma.rn.f32x2 %0, %1, %2, %0;" : "+l"(acc) : "l"(a), "l"(b));
}

// ---------------------------------------------------------------------------
// Kernel 2: fused distance-GEMM + per-split top-5 on d' = y2 - 2*dot
//   grid = (SPLITS, N_Q/QT), block = 256 (16 tx x 16 ty), 4x4 micro-tile
// Dynamic smem layout (floats):
//   As2  [QT][DIM*2]      duplicated (a,a) pairs : 16384 floats (64 KB)
//   Bs   [DIM][BT]        k-major, XOR-swizzled  :  8192 floats (32 KB)
//   y2s  [BT]                                    :    64 floats
//   merge buffer reuses Bs (needs QT*16*KNN = 5120 floats)
// ---------------------------------------------------------------------------
__global__ void __launch_bounds__(TPB, 2)
phaseA(const float* __restrict__ feat, const float* __restrict__ bank) {
    extern __shared__ float smem[];
    float* As2  = smem;                   // 16384
    float* Bs   = smem + 16384;           // 8192
    float* y2s  = smem + 16384 + 8192;    // 64
    float* mbuf = Bs;                     // merge reuse

    const int tid = threadIdx.x;
    const int tx = tid & 15;
    const int ty = tid >> 4;
    const int split = blockIdx.x;
    const int q0 = blockIdx.y * QT;

    // ---- stage A tile once (duplicated pairs for f32x2 broadcast) ----
    #pragma unroll
    for (int it = 0; it < (QT * DIM / 4) / TPB; ++it) {   // 8 iters
        int f = it * TPB + tid;
        int q = f >> 5;                 // 0..63
        int k4 = (f & 31) << 2;         // 0..124
        float4 v = *reinterpret_cast<const float4*>(feat + (size_t)(q0 + q) * DIM + k4);
        float2* dst = reinterpret_cast<float2*>(As2 + q * (DIM * 2) + k4 * 2);
        dst[0] = make_float2(v.x, v.x);
        dst[1] = make_float2(v.y, v.y);
        dst[2] = make_float2(v.z, v.z);
        dst[3] = make_float2(v.w, v.w);
    }

    const int rbase = split * ROWS_PER_SPLIT;
    const int rend  = min(rbase + ROWS_PER_SPLIT, M_B);

    float top[4][KNN];
    #pragma unroll
    for (int i = 0; i < 4; ++i)
        #pragma unroll
        for (int s = 0; s < KNN; ++s) top[i][s] = FLT_MAX;

    const float* Arow[4];
    #pragma unroll
    for (int i = 0; i < 4; ++i) Arow[i] = As2 + (ty * 4 + i) * (DIM * 2);

    for (int t = 0; t < TILES_PER_SPLIT; ++t) {
        int r0 = rbase + t * BT;
        if (r0 >= rend) break;          // uniform across block
        __syncthreads();                // protect Bs from previous tile readers

        // ---- stage B tile, k-major with XOR chunk swizzle ----
        // logical (k, b)  ->  float idx  k*BT + (((b>>2) ^ ((k>>2)&15))<<2) + (b&3)
        #pragma unroll
        for (int it = 0; it < (BT * DIM / 4) / TPB; ++it) {  // 8 iters
            int f = it * TPB + tid;
            int b = f >> 5;             // 0..63
            int k4pos = f & 31;         // k = 4*k4pos
            int r = r0 + b;
            float4 v = (r < rend)
                ? *reinterpret_cast<const float4*>(bank + (size_t)r * DIM + (k4pos << 2))
                : make_float4(0.f, 0.f, 0.f, 0.f);
            int chunk = (b >> 2) ^ (k4pos & 15);
            int base = (k4pos << 2) * BT + (chunk << 2) + (b & 3);
            Bs[base]          = v.x;
            Bs[base + BT]     = v.y;
            Bs[base + 2 * BT] = v.z;
            Bs[base + 3 * BT] = v.w;
        }
        if (tid < BT) {
            int r = r0 + tid;
            y2s[tid] = (r < rend) ? g_y2[r] : FLT_MAX;
        }
        __syncthreads();

        // ---- 4x4 micro-tile dot products over K=128, packed f32x2 ----
        u64 acc[4][2];
        #pragma unroll
        for (int i = 0; i < 4; ++i) { acc[i][0] = 0ULL; acc[i][1] = 0ULL; }

        #pragma unroll 2
        for (int k4 = 0; k4 < DIM / 4; ++k4) {
            int chunk = tx ^ (k4 & 15);
            const float* bp = Bs + (k4 << 2) * BT + (chunk << 2);
            #pragma unroll
            for (int kk = 0; kk < 4; ++kk) {
                u64 b01 = *reinterpret_cast<const u64*>(bp + kk * BT);
                u64 b23 = *reinterpret_cast<const u64*>(bp + kk * BT + 2);
                int k = (k4 << 2) + kk;
                #pragma unroll
                for (int i = 0; i < 4; ++i) {
                    u64 a = *reinterpret_cast<const u64*>(Arow[i] + 2 * k);
                    fma2(acc[i][0], a, b01);
                    fma2(acc[i][1], a, b23);
                }
            }
        }

        // ---- top-5 update on d' = y2 - 2*dot ----
        float yv0 = y2s[tx * 4 + 0];
        float yv1 = y2s[tx * 4 + 1];
        float yv2 = y2s[tx * 4 + 2];
        float yv3 = y2s[tx * 4 + 3];
        #pragma unroll
        for (int i = 0; i < 4; ++i) {
            float d0, d1, d2, d3;
            asm("mov.b64 {%0, %1}, %2;" : "=f"(d0), "=f"(d1) : "l"(acc[i][0]));
            asm("mov.b64 {%0, %1}, %2;" : "=f"(d2), "=f"(d3) : "l"(acc[i][1]));
            d0 = yv0 - 2.0f * d0;
            d1 = yv1 - 2.0f * d1;
            d2 = yv2 - 2.0f * d2;
            d3 = yv3 - 2.0f * d3;
            if (d0 < top[i][KNN - 1]) insert5(top[i], d0);
            if (d1 < top[i][KNN - 1]) insert5(top[i], d1);
            if (d2 < top[i][KNN - 1]) insert5(top[i], d2);
            if (d3 < top[i][KNN - 1]) insert5(top[i], d3);
        }
    }

    // ---- merge 16 threads' top-5 per query, write split candidates ----
    __syncthreads();
    #pragma unroll
    for (int i = 0; i < 4; ++i) {
        int q = ty * 4 + i;
        float* dst = mbuf + (q * 16 + tx) * KNN;
        #pragma unroll
        for (int s = 0; s < KNN; ++s) dst[s] = top[i][s];
    }
    __syncthreads();
    if (tid < QT) {
        float best[KNN];
        #pragma unroll
        for (int s = 0; s < KNN; ++s) best[s] = FLT_MAX;
        const float* src = mbuf + tid * 16 * KNN;
        for (int c = 0; c < 16 * KNN; ++c) {
            float d = src[c];
            if (d < best[KNN - 1]) insert5(best, d);
        }
        float* dst = g_scratch + ((size_t)(q0 + tid) * SPLITS + split) * KNN;
        #pragma unroll
        for (int s = 0; s < KNN; ++s) dst[s] = best[s];
    }
}

// ---------------------------------------------------------------------------
// Kernel 3: final merge + x^2 + sqrt + normalize + mean
// ---------------------------------------------------------------------------
__global__ void phaseB(const float* __restrict__ feat,
                       const float* __restrict__ minv,
                       const float* __restrict__ maxv,
                       float* __restrict__ out) {
    int q = blockIdx.x * blockDim.x + threadIdx.x;
    if (q >= N_Q) return;

    float best[KNN];
    #pragma unroll
    for (int s = 0; s < KNN; ++s) best[s] = FLT_MAX;
    const float* src = g_scratch + (size_t)q * SPLITS * KNN;
    #pragma unroll 5
    for (int c = 0; c < SPLITS * KNN; ++c) {
        float d = src[c];
        if (d < best[KNN - 1]) insert5(best, d);
    }

    const float4* fr = reinterpret_cast<const float4*>(feat + (size_t)q * DIM);
    float x2 = 0.f;
    #pragma unroll
    for (int i = 0; i < DIM / 4; ++i) {
        float4 v = fr[i];
        x2 += v.x * v.x + v.y * v.y + v.z * v.z + v.w * v.w;
    }

    float mn = *minv, mx = *maxv;
    float inv = 1.0f / (mx - mn);
    float acc = 0.f;
    #pragma unroll
    for (int s = 0; s < KNN; ++s) {
        float d2 = fmaxf(x2 + best[s], 0.f);
        acc += (sqrtf(d2) - mn) * inv;
    }
    out[q] = acc * (1.0f / (float)KNN);
}

// ---------------------------------------------------------------------------
extern "C" void kernel_launch(void* const* d_in, const int* in_sizes, int n_in,
                              void* d_out, int out_size) {
    (void)in_sizes; (void)n_in; (void)out_size;
    const float* feat = (const float*)d_in[0];
    const float* bank = (const float*)d_in[1];
    const float* minv = (const float*)d_in[2];
    const float* maxv = (const float*)d_in[3];
    float* out = (float*)d_out;

    y2_kernel<<<(M_B + 7) / 8, 256>>>(bank);

    int smem_bytes = (16384 + 8192 + 64) * 4;   // 98560 B
    cudaFuncSetAttribute(phaseA, cudaFuncAttributeMaxDynamicSharedMemorySize, smem_bytes);
    phaseA<<<dim3(SPLITS, N_Q / QT), TPB, smem_bytes>>>(feat, bank);

    phaseB<<<(N_Q + 255) / 256, 256>>>(feat, minv, maxv, out);
}

// round 4
// speedup vs baseline: 3.7219x; 3.7219x over previous
#include <cuda_runtime.h>
#include <cuda_bf16.h>
#include <cfloat>
#include <cstdint>

#define N_Q    2048
#define M_B    100000
#define M_PAD  100224
#define KNN    5
#define SPLITS 37
#define RPS    2703            /* 37*2703 = 100011 >= 100000 */
#define BT     64
#define NT     43              /* ceil(2703/64); max row touched 100060 < M_PAD */
#define QTILES 16

// ---------------------------------------------------------------------------
// device scratch
// ---------------------------------------------------------------------------
__device__ __align__(256) __nv_bfloat16 g_bank2[(size_t)M_PAD * 256];
__device__ __align__(256) __nv_bfloat16 g_feat2[(size_t)N_Q * 256];
__device__ float g_y2p[M_PAD];
__device__ float g_scratch[(size_t)N_Q * SPLITS * KNN];

#define SWZ(o) ((o) ^ (((o) >> 3) & 0x70))

__device__ __forceinline__ uint32_t smem_u32(const void* p) {
    uint32_t a;
    asm("{ .reg .u64 t; cvta.to.shared.u64 t, %1; cvt.u32.u64 %0, t; }" : "=r"(a) : "l"(p));
    return a;
}

#define CP16(dst, src) asm volatile("cp.async.cg.shared.global [%0], [%1], 16;" :: "r"(dst), "l"(src))
#define CP_COMMIT()    asm volatile("cp.async.commit_group;" ::: "memory")
#define CP_WAIT1()     asm volatile("cp.async.wait_group 1;" ::: "memory")
#define CP_WAIT0()     asm volatile("cp.async.wait_group 0;" ::: "memory")

#define LDSM4(r0, r1, r2, r3, a)                                               \
    asm volatile("ldmatrix.sync.aligned.m8n8.x4.shared.b16 {%0,%1,%2,%3}, [%4];" \
        : "=r"(r0), "=r"(r1), "=r"(r2), "=r"(r3) : "r"(a))

__device__ __forceinline__ void mma16816(float* c,
    uint32_t a0, uint32_t a1, uint32_t a2, uint32_t a3, uint32_t b0, uint32_t b1) {
    asm("mma.sync.aligned.m16n8k16.row.col.f32.bf16.bf16.f32 "
        "{%0,%1,%2,%3}, {%4,%5,%6,%7}, {%8,%9}, {%0,%1,%2,%3};"
        : "+f"(c[0]), "+f"(c[1]), "+f"(c[2]), "+f"(c[3])
        : "r"(a0), "r"(a1), "r"(a2), "r"(a3), "r"(b0), "r"(b1));
}

__device__ __forceinline__ void insert5(float* t, float d) {
    t[4] = d;
#pragma unroll
    for (int s = 4; s > 0; --s) {
        float lo = fminf(t[s], t[s - 1]);
        float hi = fmaxf(t[s], t[s - 1]);
        t[s - 1] = lo; t[s] = hi;
    }
}

// ---------------------------------------------------------------------------
// prep: fp32 -> (hi, lo) bf16 pairs; bank also y2 (+INF padding)
// ---------------------------------------------------------------------------
__global__ void prep_bank(const float* __restrict__ bank) {
    int r = (blockIdx.x * blockDim.x + threadIdx.x) >> 5;
    int lane = threadIdx.x & 31;
    if (r >= M_PAD) return;
    float4 v = make_float4(0.f, 0.f, 0.f, 0.f);
    if (r < M_B) v = *reinterpret_cast<const float4*>(bank + (size_t)r * 128 + lane * 4);
    float f[4] = {v.x, v.y, v.z, v.w};
    __nv_bfloat16 h[4], l[4];
#pragma unroll
    for (int i = 0; i < 4; ++i) {
        h[i] = __float2bfloat16(f[i]);
        l[i] = __float2bfloat16(f[i] - __bfloat162float(h[i]));
    }
    *reinterpret_cast<uint2*>(&g_bank2[(size_t)r * 256 + lane * 4])       = *reinterpret_cast<const uint2*>(h);
    *reinterpret_cast<uint2*>(&g_bank2[(size_t)r * 256 + 128 + lane * 4]) = *reinterpret_cast<const uint2*>(l);
    float s = v.x * v.x + v.y * v.y + v.z * v.z + v.w * v.w;
#pragma unroll
    for (int o = 16; o; o >>= 1) s += __shfl_xor_sync(0xFFFFFFFFu, s, o);
    if (lane == 0) g_y2p[r] = (r < M_B) ? s : __int_as_float(0x7f800000);
}

__global__ void prep_feat(const float* __restrict__ feat) {
    int r = (blockIdx.x * blockDim.x + threadIdx.x) >> 5;
    int lane = threadIdx.x & 31;
    if (r >= N_Q) return;
    float4 v = *reinterpret_cast<const float4*>(feat + (size_t)r * 128 + lane * 4);
    float f[4] = {v.x, v.y, v.z, v.w};
    __nv_bfloat16 h[4], l[4];
#pragma unroll
    for (int i = 0; i < 4; ++i) {
        h[i] = __float2bfloat16(f[i]);
        l[i] = __float2bfloat16(f[i] - __bfloat162float(h[i]));
    }
    *reinterpret_cast<uint2*>(&g_feat2[(size_t)r * 256 + lane * 4])       = *reinterpret_cast<const uint2*>(h);
    *reinterpret_cast<uint2*>(&g_feat2[(size_t)r * 256 + 128 + lane * 4]) = *reinterpret_cast<const uint2*>(l);
}

// ---------------------------------------------------------------------------
// main: 128q x 64m x K256 bf16 HMMA + fused top-5
// smem: A 64KB @0 (4 chunks x 16KB), B 2x32KB @65536 (4 chunks x 8KB each),
//       y2 2x256B @131072. merge buffer reuses B region.
// ---------------------------------------------------------------------------
#define SMEM_SZ 131584

__global__ void __launch_bounds__(256, 1)
knn_main() {
    extern __shared__ __align__(1024) char smem[];
    const uint32_t sb = smem_u32(smem);
    const int tid  = threadIdx.x;
    const int wid  = tid >> 5;
    const int lane = tid & 31;
    const int wq = (wid >> 1) * 32;     // warp q offset (0,32,64,96)
    const int wm = (wid & 1) * 32;      // warp m offset (0,32)

    const int split  = blockIdx.x;
    const int q0     = blockIdx.y * 128;
    const int rbegin = split * RPS;
    const int rend   = min(rbegin + RPS, M_B);

    // ---- A tile: 128 rows x 512B, swizzled, loaded once ----
    {
        const char* ga = (const char*)g_feat2 + (size_t)q0 * 512;
        for (int seg = tid; seg < 4096; seg += 256) {
            int row = seg >> 5, by = (seg & 31) << 4;
            int ch = by >> 7, inb = by & 127;
            float4 v = *reinterpret_cast<const float4*>(ga + row * 512 + by);
            *reinterpret_cast<float4*>(smem + ch * 16384 + SWZ(row * 128 + inb)) = v;
        }
    }

    // ---- lane-invariant fragment addresses ----
    const int ka = (lane & 16) ? 16 : 0;             // A k-half byte
    uint32_t aBase[2]; int xa[2];
#pragma unroll
    for (int mt = 0; mt < 2; ++mt) {
        int mrow = wq + mt * 16 + (lane & 15);
        aBase[mt] = sb + mrow * 128;
        xa[mt] = (mrow & 7) * 16;
    }
    const int kb = ((lane >> 4) & 1) * 16;           // B k-half byte
    const int nr = ((lane >> 3) & 1) * 8 + (lane & 7);
    uint32_t bRel[2]; int xb[2];
#pragma unroll
    for (int g = 0; g < 2; ++g) {
        int nrow = wm + g * 16 + nr;
        bRel[g] = nrow * 128;
        xb[g] = (nrow & 7) * 16;
    }

    // ---- B stage helper (y2 staged with plain LDG/STS: r0 is odd-aligned) ----
    auto stageB = [&](int st, int r0) {
        const char* gb = (const char*)g_bank2 + (size_t)r0 * 512;
        uint32_t bs = sb + 65536 + st * 32768;
#pragma unroll
        for (int it = 0; it < 8; ++it) {
            int seg = it * 256 + tid;
            int row = seg >> 5, by = (seg & 31) << 4;
            int ch = by >> 7, inb = by & 127;
            CP16(bs + ch * 8192 + SWZ(row * 128 + inb), gb + row * 512 + by);
        }
        CP_COMMIT();
        if (tid < BT)
            ((float*)(smem + 131072 + st * 256))[tid] = g_y2p[r0 + tid];
    };

    stageB(0, rbegin);

    float top[4][KNN];
#pragma unroll
    for (int i = 0; i < 4; ++i)
#pragma unroll
        for (int s = 0; s < KNN; ++s) top[i][s] = FLT_MAX;

    const float INF = __int_as_float(0x7f800000);

    for (int t = 0; t < NT; ++t) {
        const int st = t & 1;
        const int r0 = rbegin + t * BT;
        if (t + 1 < NT) { stageB(st ^ 1, r0 + BT); CP_WAIT1(); }
        else            { CP_WAIT0(); }
        __syncthreads();

        // ---- compute: 16 k-steps ----
        float acc[2][4][4];
#pragma unroll
        for (int mt = 0; mt < 2; ++mt)
#pragma unroll
            for (int nt = 0; nt < 4; ++nt)
#pragma unroll
                for (int c = 0; c < 4; ++c) acc[mt][nt][c] = 0.f;

        const uint32_t bs = sb + 65536 + st * 32768;
#pragma unroll
        for (int ks = 0; ks < 16; ++ks) {
            const uint32_t ca = (ks >> 2) * 16384u;
            const uint32_t cb = (ks >> 2) * 8192u;
            const int kk = (ks & 3) * 32;
            uint32_t A[2][4], B[2][4];
            LDSM4(A[0][0], A[0][1], A[0][2], A[0][3], aBase[0] + ca + ((kk + ka) ^ xa[0]));
            LDSM4(A[1][0], A[1][1], A[1][2], A[1][3], aBase[1] + ca + ((kk + ka) ^ xa[1]));
            LDSM4(B[0][0], B[0][1], B[0][2], B[0][3], bs + cb + bRel[0] + ((kk + kb) ^ xb[0]));
            LDSM4(B[1][0], B[1][1], B[1][2], B[1][3], bs + cb + bRel[1] + ((kk + kb) ^ xb[1]));
#pragma unroll
            for (int mt = 0; mt < 2; ++mt)
#pragma unroll
                for (int nt = 0; nt < 4; ++nt)
                    mma16816(acc[mt][nt], A[mt][0], A[mt][1], A[mt][2], A[mt][3],
                             B[nt >> 1][nt & 1], B[nt >> 1][(nt & 1) + 2]);
        }

        // ---- fused epilogue: d' = y2 - 2*dot, per-thread top-5 ----
        const float* y2s = (const float*)(smem + 131072 + st * 256);
        const int lim = rend - r0;      // valid columns in this tile
#pragma unroll
        for (int nt = 0; nt < 4; ++nt) {
#pragma unroll
            for (int j = 0; j < 2; ++j) {
                int col = wm + (nt >> 1) * 16 + (nt & 1) * 8 + (lane & 3) * 2 + j;
                float yv = (col < lim) ? y2s[col] : INF;
#pragma unroll
                for (int mt = 0; mt < 2; ++mt) {
#pragma unroll
                    for (int half = 0; half < 2; ++half) {
                        float d = fmaf(-2.0f, acc[mt][nt][half * 2 + j], yv);
                        int ti = mt * 2 + half;
                        if (d < top[ti][KNN - 1]) insert5(top[ti], d);
                    }
                }
            }
        }
        __syncthreads();
    }

    // ---- merge 8 lists per query through smem (reuse B region) ----
    float* mbuf = (float*)(smem + 65536);
    const int lid = (wid & 1) * 4 + (lane & 3);
#pragma unroll
    for (int ti = 0; ti < 4; ++ti) {
        int mt = ti >> 1, half = ti & 1;
        int qloc = wq + mt * 16 + half * 8 + (lane >> 2);
        float* dst = mbuf + (qloc * 8 + lid) * KNN;
#pragma unroll
        for (int s = 0; s < KNN; ++s) dst[s] = top[ti][s];
    }
    __syncthreads();
    if (tid < 128) {
        float best[KNN] = {FLT_MAX, FLT_MAX, FLT_MAX, FLT_MAX, FLT_MAX};
        const float* src = mbuf + tid * 8 * KNN;
#pragma unroll
        for (int c = 0; c < 8 * KNN; ++c) {
            float d = src[c];
            if (d < best[KNN - 1]) insert5(best, d);
        }
        float* dst = g_scratch + ((size_t)(q0 + tid) * SPLITS + split) * KNN;
#pragma unroll
        for (int s = 0; s < KNN; ++s) dst[s] = best[s];
    }
}

// ---------------------------------------------------------------------------
// final merge + x^2 + sqrt + normalize + mean
// ---------------------------------------------------------------------------
__global__ void phaseB(const float* __restrict__ feat,
                       const float* __restrict__ minv,
                       const float* __restrict__ maxv,
                       float* __restrict__ out) {
    int q = blockIdx.x * blockDim.x + threadIdx.x;
    if (q >= N_Q) return;

    float best[KNN] = {FLT_MAX, FLT_MAX, FLT_MAX, FLT_MAX, FLT_MAX};
    const float* src = g_scratch + (size_t)q * SPLITS * KNN;
    for (int c = 0; c < SPLITS * KNN; ++c) {
        float d = src[c];
        if (d < best[KNN - 1]) insert5(best, d);
    }

    const float4* fr = reinterpret_cast<const float4*>(feat + (size_t)q * 128);
    float x2 = 0.f;
#pragma unroll
    for (int i = 0; i < 32; ++i) {
        float4 v = fr[i];
        x2 += v.x * v.x + v.y * v.y + v.z * v.z + v.w * v.w;
    }

    float mn = *minv, mx = *maxv;
    float inv = 1.0f / (mx - mn);
    float acc = 0.f;
#pragma unroll
    for (int s = 0; s < KNN; ++s) {
        float d2 = fmaxf(x2 + best[s], 0.f);
        acc += (sqrtf(d2) - mn) * inv;
    }
    out[q] = acc * (1.0f / (float)KNN);
}

// ---------------------------------------------------------------------------
extern "C" void kernel_launch(void* const* d_in, const int* in_sizes, int n_in,
                              void* d_out, int out_size) {
    (void)in_sizes; (void)n_in; (void)out_size;
    const float* feat = (const float*)d_in[0];
    const float* bank = (const float*)d_in[1];
    const float* minv = (const float*)d_in[2];
    const float* maxv = (const float*)d_in[3];
    float* out = (float*)d_out;

    prep_bank<<<(M_PAD + 7) / 8, 256>>>(bank);
    prep_feat<<<(N_Q + 7) / 8, 256>>>(feat);

    cudaFuncSetAttribute(knn_main, cudaFuncAttributeMaxDynamicSharedMemorySize, SMEM_SZ);
    knn_main<<<dim3(SPLITS, QTILES), 256, SMEM_SZ>>>();

    phaseB<<<(N_Q + 255) / 256, 256>>>(feat, minv, maxv, out);
}

// round 5
// speedup vs baseline: 6.8905x; 1.8513x over previous
#include <cuda_runtime.h>
#include <cuda_bf16.h>
#include <cfloat>
#include <cstdint>

#define N_Q    2048
#define M_B    100000
#define M_PAD  100224
#define KNN    5
#define SPLITS 37
#define RPS    2703            /* 37*2703 = 100011 >= 100000 */
#define BT     128
#define NT     22              /* ceil(2703/128); max staged row 100124 < M_PAD */
#define QTILES 16
#define NCAND  (SPLITS * KNN)  /* 185 */

// ---------------------------------------------------------------------------
// device scratch (bf16 hi only: 256 B per row)
// ---------------------------------------------------------------------------
__device__ __align__(256) __nv_bfloat16 g_bank1[(size_t)M_PAD * 128];
__device__ __align__(256) __nv_bfloat16 g_feat1[(size_t)N_Q * 128];
__device__ float g_y2p[M_PAD];
__device__ float g_scratch[(size_t)N_Q * NCAND];

#define SWZ(o) ((o) ^ (((o) >> 3) & 0x70))

__device__ __forceinline__ uint32_t smem_u32(const void* p) {
    uint32_t a;
    asm("{ .reg .u64 t; cvta.to.shared.u64 t, %1; cvt.u32.u64 %0, t; }" : "=r"(a) : "l"(p));
    return a;
}

#define CP16(dst, src) asm volatile("cp.async.cg.shared.global [%0], [%1], 16;" :: "r"(dst), "l"(src))
#define CP_COMMIT()    asm volatile("cp.async.commit_group;" ::: "memory")
#define CP_WAIT1()     asm volatile("cp.async.wait_group 1;" ::: "memory")
#define CP_WAIT0()     asm volatile("cp.async.wait_group 0;" ::: "memory")

#define LDSM4(r0, r1, r2, r3, a)                                               \
    asm volatile("ldmatrix.sync.aligned.m8n8.x4.shared.b16 {%0,%1,%2,%3}, [%4];" \
        : "=r"(r0), "=r"(r1), "=r"(r2), "=r"(r3) : "r"(a))

__device__ __forceinline__ void mma16816(float* c,
    uint32_t a0, uint32_t a1, uint32_t a2, uint32_t a3, uint32_t b0, uint32_t b1) {
    asm("mma.sync.aligned.m16n8k16.row.col.f32.bf16.bf16.f32 "
        "{%0,%1,%2,%3}, {%4,%5,%6,%7}, {%8,%9}, {%0,%1,%2,%3};"
        : "+f"(c[0]), "+f"(c[1]), "+f"(c[2]), "+f"(c[3])
        : "r"(a0), "r"(a1), "r"(a2), "r"(a3), "r"(b0), "r"(b1));
}

__device__ __forceinline__ void insert5(float* t, float d) {
    t[4] = d;
#pragma unroll
    for (int s = 4; s > 0; --s) {
        float lo = fminf(t[s], t[s - 1]);
        float hi = fmaxf(t[s], t[s - 1]);
        t[s - 1] = lo; t[s] = hi;
    }
}

// ---------------------------------------------------------------------------
// prep: fp32 -> bf16 hi; bank also y2 (+INF padding)
// ---------------------------------------------------------------------------
__global__ void prep_bank(const float* __restrict__ bank) {
    int r = (blockIdx.x * blockDim.x + threadIdx.x) >> 5;
    int lane = threadIdx.x & 31;
    if (r >= M_PAD) return;
    float4 v = make_float4(0.f, 0.f, 0.f, 0.f);
    if (r < M_B) v = *reinterpret_cast<const float4*>(bank + (size_t)r * 128 + lane * 4);
    __nv_bfloat16 h[4] = {__float2bfloat16(v.x), __float2bfloat16(v.y),
                          __float2bfloat16(v.z), __float2bfloat16(v.w)};
    *reinterpret_cast<uint2*>(&g_bank1[(size_t)r * 128 + lane * 4]) = *reinterpret_cast<const uint2*>(h);
    float s = v.x * v.x + v.y * v.y + v.z * v.z + v.w * v.w;
#pragma unroll
    for (int o = 16; o; o >>= 1) s += __shfl_xor_sync(0xFFFFFFFFu, s, o);
    if (lane == 0) g_y2p[r] = (r < M_B) ? s : __int_as_float(0x7f800000);
}

__global__ void prep_feat(const float* __restrict__ feat) {
    int r = (blockIdx.x * blockDim.x + threadIdx.x) >> 5;
    int lane = threadIdx.x & 31;
    if (r >= N_Q) return;
    float4 v = *reinterpret_cast<const float4*>(feat + (size_t)r * 128 + lane * 4);
    __nv_bfloat16 h[4] = {__float2bfloat16(v.x), __float2bfloat16(v.y),
                          __float2bfloat16(v.z), __float2bfloat16(v.w)};
    *reinterpret_cast<uint2*>(&g_feat1[(size_t)r * 128 + lane * 4]) = *reinterpret_cast<const uint2*>(h);
}

// ---------------------------------------------------------------------------
// main: 128q x 128m x K128 bf16 HMMA + fused top-5, occ 2
// smem: A 32KB @0 (2 chunks x 16KB) | B 2x32KB @32768 | y2 2x512B @98304
// ---------------------------------------------------------------------------
#define SMEM_SZ 99328

__global__ void __launch_bounds__(256, 2)
knn_main() {
    extern __shared__ __align__(1024) char smem[];
    const uint32_t sb = smem_u32(smem);
    const int tid  = threadIdx.x;
    const int wid  = tid >> 5;
    const int lane = tid & 31;
    const int wq = (wid >> 1) * 32;     // 0,32,64,96
    const int wm = (wid & 1) * 64;      // 0,64

    const int split  = blockIdx.x;
    const int q0     = blockIdx.y * 128;
    const int rbegin = split * RPS;
    const int rend   = min(rbegin + RPS, M_B);

    // ---- A tile: 128 rows x 256B, swizzled, loaded once ----
    {
        const char* ga = (const char*)g_feat1 + (size_t)q0 * 256;
#pragma unroll
        for (int it = 0; it < 8; ++it) {
            int seg = it * 256 + tid;
            int row = seg >> 4, by = (seg & 15) << 4;
            int ch = by >> 7, inb = by & 127;
            float4 v = *reinterpret_cast<const float4*>(ga + row * 256 + by);
            *reinterpret_cast<float4*>(smem + ch * 16384 + SWZ(row * 128 + inb)) = v;
        }
    }

    // ---- lane-invariant fragment addresses ----
    const int ka = (lane & 16) ? 16 : 0;
    uint32_t aBase[2]; int xa[2];
#pragma unroll
    for (int mt = 0; mt < 2; ++mt) {
        int mrow = wq + mt * 16 + (lane & 15);
        aBase[mt] = sb + mrow * 128;
        xa[mt] = (mrow & 7) * 16;
    }
    const int kb = ((lane >> 4) & 1) * 16;
    const int nr = ((lane >> 3) & 1) * 8 + (lane & 7);
    uint32_t bRel[4]; int xb[4];
#pragma unroll
    for (int g = 0; g < 4; ++g) {
        int nrow = wm + g * 16 + nr;
        bRel[g] = nrow * 128;
        xb[g] = (nrow & 7) * 16;
    }

    // ---- B stage (y2 via plain LDG/STS: r0 only 4B-aligned) ----
    auto stageB = [&](int st, int r0) {
        const char* gb = (const char*)g_bank1 + (size_t)r0 * 256;
        uint32_t bs = sb + 32768 + st * 32768;
#pragma unroll
        for (int it = 0; it < 8; ++it) {
            int seg = it * 256 + tid;
            int row = seg >> 4, by = (seg & 15) << 4;
            int ch = by >> 7, inb = by & 127;
            CP16(bs + ch * 16384 + SWZ(row * 128 + inb), gb + row * 256 + by);
        }
        CP_COMMIT();
        if (tid < BT)
            ((float*)(smem + 98304 + st * 512))[tid] = g_y2p[r0 + tid];
    };

    stageB(0, rbegin);

    float top[4][KNN];
#pragma unroll
    for (int i = 0; i < 4; ++i)
#pragma unroll
        for (int s = 0; s < KNN; ++s) top[i][s] = FLT_MAX;

    const float INF = __int_as_float(0x7f800000);

    for (int t = 0; t < NT; ++t) {
        const int st = t & 1;
        const int r0 = rbegin + t * BT;
        if (t + 1 < NT) { stageB(st ^ 1, r0 + BT); CP_WAIT1(); }
        else            { CP_WAIT0(); }
        __syncthreads();

        float acc[2][8][4];
#pragma unroll
        for (int mt = 0; mt < 2; ++mt)
#pragma unroll
            for (int nt = 0; nt < 8; ++nt)
#pragma unroll
                for (int c = 0; c < 4; ++c) acc[mt][nt][c] = 0.f;

        const uint32_t bs = sb + 32768 + st * 32768;
#pragma unroll
        for (int ks = 0; ks < 8; ++ks) {
            const uint32_t ca = (ks >> 2) * 16384u;
            const int kk = (ks & 3) * 32;
            uint32_t A[2][4], B[4][4];
            LDSM4(A[0][0], A[0][1], A[0][2], A[0][3], aBase[0] + ca + ((kk + ka) ^ xa[0]));
            LDSM4(A[1][0], A[1][1], A[1][2], A[1][3], aBase[1] + ca + ((kk + ka) ^ xa[1]));
#pragma unroll
            for (int g = 0; g < 4; ++g)
                LDSM4(B[g][0], B[g][1], B[g][2], B[g][3],
                      bs + ca + bRel[g] + ((kk + kb) ^ xb[g]));
#pragma unroll
            for (int mt = 0; mt < 2; ++mt)
#pragma unroll
                for (int nt = 0; nt < 8; ++nt)
                    mma16816(acc[mt][nt], A[mt][0], A[mt][1], A[mt][2], A[mt][3],
                             B[nt >> 1][nt & 1], B[nt >> 1][(nt & 1) + 2]);
        }

        // ---- fused epilogue ----
        const float* y2s = (const float*)(smem + 98304 + st * 512);
        const int lim = rend - r0;
#pragma unroll
        for (int nt = 0; nt < 8; ++nt) {
#pragma unroll
            for (int j = 0; j < 2; ++j) {
                int col = wm + nt * 8 + (lane & 3) * 2 + j;
                float yv = (col < lim) ? y2s[col] : INF;
#pragma unroll
                for (int mt = 0; mt < 2; ++mt) {
#pragma unroll
                    for (int half = 0; half < 2; ++half) {
                        float d = fmaf(-2.0f, acc[mt][nt][half * 2 + j], yv);
                        int ti = mt * 2 + half;
                        if (d < top[ti][KNN - 1]) insert5(top[ti], d);
                    }
                }
            }
        }
        __syncthreads();
    }

    // ---- merge 8 lists per query through smem (reuse B region) ----
    float* mbuf = (float*)(smem + 32768);
    const int lid = (wid & 1) * 4 + (lane & 3);
#pragma unroll
    for (int ti = 0; ti < 4; ++ti) {
        int mt = ti >> 1, half = ti & 1;
        int qloc = wq + mt * 16 + half * 8 + (lane >> 2);
        float* dst = mbuf + (qloc * 8 + lid) * KNN;
#pragma unroll
        for (int s = 0; s < KNN; ++s) dst[s] = top[ti][s];
    }
    __syncthreads();
    if (tid < 128) {
        float best[KNN] = {FLT_MAX, FLT_MAX, FLT_MAX, FLT_MAX, FLT_MAX};
        const float* src = mbuf + tid * 8 * KNN;
#pragma unroll
        for (int c = 0; c < 8 * KNN; ++c) {
            float d = src[c];
            if (d < best[KNN - 1]) insert5(best, d);
        }
        float* dst = g_scratch + ((size_t)(q0 + tid) * SPLITS + split) * KNN;
#pragma unroll
        for (int s = 0; s < KNN; ++s) dst[s] = best[s];
    }
}

// ---------------------------------------------------------------------------
// phaseB: one warp per query — 5-pass warp-min select over 185 candidates
// ---------------------------------------------------------------------------
__global__ void phaseB(const float* __restrict__ feat,
                       const float* __restrict__ minv,
                       const float* __restrict__ maxv,
                       float* __restrict__ out) {
    const int lane = threadIdx.x & 31;
    const int q = blockIdx.x * (blockDim.x >> 5) + (threadIdx.x >> 5);
    if (q >= N_Q) return;

    const float INF = __int_as_float(0x7f800000);
    const float* src = g_scratch + (size_t)q * NCAND;
    float v[6];
#pragma unroll
    for (int i = 0; i < 6; ++i) {
        int idx = i * 32 + lane;
        v[i] = (idx < NCAND) ? src[idx] : INF;
    }

    // x2 warp-reduced
    float4 fv = *reinterpret_cast<const float4*>(feat + (size_t)q * 128 + lane * 4);
    float x2 = fv.x * fv.x + fv.y * fv.y + fv.z * fv.z + fv.w * fv.w;
#pragma unroll
    for (int o = 16; o; o >>= 1) x2 += __shfl_xor_sync(0xFFFFFFFFu, x2, o);

    float best[KNN];
#pragma unroll
    for (int p = 0; p < KNN; ++p) {
        float lm = v[0];
#pragma unroll
        for (int i = 1; i < 6; ++i) lm = fminf(lm, v[i]);
        float wm = lm;
#pragma unroll
        for (int o = 16; o; o >>= 1) wm = fminf(wm, __shfl_xor_sync(0xFFFFFFFFu, wm, o));
        unsigned mask = __ballot_sync(0xFFFFFFFFu, lm == wm);
        int leader = __ffs(mask) - 1;
        if (lane == leader) {
            bool done = false;
#pragma unroll
            for (int i = 0; i < 6; ++i)
                if (!done && v[i] == wm) { v[i] = INF; done = true; }
        }
        best[p] = wm;
    }

    if (lane == 0) {
        float mn = *minv, mx = *maxv;
        float inv = 1.0f / (mx - mn);
        float acc = 0.f;
#pragma unroll
        for (int s = 0; s < KNN; ++s) {
            float d2 = fmaxf(x2 + best[s], 0.f);
            acc += (sqrtf(d2) - mn) * inv;
        }
        out[q] = acc * (1.0f / (float)KNN);
    }
}

// ---------------------------------------------------------------------------
extern "C" void kernel_launch(void* const* d_in, const int* in_sizes, int n_in,
                              void* d_out, int out_size) {
    (void)in_sizes; (void)n_in; (void)out_size;
    const float* feat = (const float*)d_in[0];
    const float* bank = (const float*)d_in[1];
    const float* minv = (const float*)d_in[2];
    const float* maxv = (const float*)d_in[3];
    float* out = (float*)d_out;

    prep_bank<<<(M_PAD + 7) / 8, 256>>>(bank);
    prep_feat<<<(N_Q + 7) / 8, 256>>>(feat);

    cudaFuncSetAttribute(knn_main, cudaFuncAttributeMaxDynamicSharedMemorySize, SMEM_SZ);
    knn_main<<<dim3(SPLITS, QTILES), 256, SMEM_SZ>>>();

    phaseB<<<(N_Q * 32 + 255) / 256, 256>>>(feat, minv, maxv, out);
}